// round 14
// baseline (speedup 1.0000x reference)
#include <cuda_runtime.h>
#include <cstdint>

#define NN 50000
#define EE 600000
#define IND 64
#define HH 128
#define NGRP 512
#define NL 3
#define BN_EPS 1e-5f
#define NB 196                       // ceil(NN/256)

#define AS_LD 132
#define WS_LD 136
#define SMEM_MLP ((64 * AS_LD + 128 * WS_LD) * 4)

// ---------------- scratch (static device arrays; no allocation) ----------------
__device__ float g_h[(size_t)NN * HH];
__device__ float g_t[(size_t)NN * HH];
__device__ float g_z[(size_t)NN * HH];
__device__ float g_vn[(size_t)NGRP * HH];
__device__ float g_pooled[(size_t)NGRP * HH];
__device__ double g_sum[HH];
__device__ double g_sumsq[HH];
__device__ float g_scale[HH];
__device__ float g_shift[HH];
__device__ float g_counts[NGRP];
// CSR scratch
__device__ int g_deg[NN];
__device__ int g_bsum[256];
__device__ int g_boff[256];
__device__ int g_rowptr[NN + 1];
__device__ int g_cursor[NN];
__device__ float4 g_csr[EE];         // (src_bits, a0, a1, pad)

__device__ __forceinline__ void red4(float* p, float4 v) {
    asm volatile("red.global.add.v4.f32 [%0], {%1,%2,%3,%4};"
                 :: "l"(p), "f"(v.x), "f"(v.y), "f"(v.z), "f"(v.w) : "memory");
}

__device__ __forceinline__ void tf32split(float x, uint32_t& hi, uint32_t& lo) {
    asm("cvt.rna.tf32.f32 %0, %1;" : "=r"(hi) : "f"(x));
    float r = x - __uint_as_float(hi);
    asm("cvt.rna.tf32.f32 %0, %1;" : "=r"(lo) : "f"(r));
}

__device__ __forceinline__ void mma8(float* c, const uint32_t* a, uint32_t b0, uint32_t b1) {
    asm volatile("mma.sync.aligned.m16n8k8.row.col.f32.tf32.tf32.f32 "
                 "{%0,%1,%2,%3}, {%4,%5,%6,%7}, {%8,%9}, {%0,%1,%2,%3};"
                 : "+f"(c[0]), "+f"(c[1]), "+f"(c[2]), "+f"(c[3])
                 : "r"(a[0]), "r"(a[1]), "r"(a[2]), "r"(a[3]), "r"(b0), "r"(b1));
}

// edge message for one 4-channel chunk
__device__ __forceinline__ void msg_acc(float4& acc, const float4 h,
                                        float a0, float a1,
                                        const float4 w0, const float4 w1,
                                        const float4 bb) {
    acc.x += fmaxf(h.x + fmaf(a0, w0.x, fmaf(a1, w1.x, bb.x)), 0.f);
    acc.y += fmaxf(h.y + fmaf(a0, w0.y, fmaf(a1, w1.y, bb.y)), 0.f);
    acc.z += fmaxf(h.z + fmaf(a0, w0.z, fmaf(a1, w1.z, bb.z)), 0.f);
    acc.w += fmaxf(h.w + fmaf(a0, w0.w, fmaf(a1, w1.w, bb.w)), 0.f);
}

// ---------------- one-time init ----------------
__global__ void zero_init_kernel() {
    int i = blockIdx.x * blockDim.x + threadIdx.x;   // 65536 threads
    if (i < NGRP * HH) g_vn[i] = 0.f;
    if (i < NGRP) g_counts[i] = 0.f;
    if (i < NN) g_deg[i] = 0;
}

__global__ void counts_kernel(const int* __restrict__ batch) {
    int i = blockIdx.x * blockDim.x + threadIdx.x;
    if (i < NN) atomicAdd(&g_counts[batch[i]], 1.f);
}

__global__ void deg_kernel(const int* __restrict__ eidx) {
    int e = blockIdx.x * blockDim.x + threadIdx.x;
    if (e < EE) atomicAdd(&g_deg[eidx[EE + e]], 1);
}

// ---- fast 3-stage scan ----
__global__ void blocksum_kernel() {               // grid NB, block 256
    __shared__ int s[256];
    int tid = threadIdx.x;
    int i = blockIdx.x * 256 + tid;
    s[tid] = (i < NN) ? g_deg[i] : 0;
    __syncthreads();
    for (int off = 128; off > 0; off >>= 1) {
        if (tid < off) s[tid] += s[tid + off];
        __syncthreads();
    }
    if (tid == 0) g_bsum[blockIdx.x] = s[0];
}

__global__ void bscan_kernel() {                  // 1 block, 256 threads
    __shared__ int s[256];
    int tid = threadIdx.x;
    int v = (tid < NB) ? g_bsum[tid] : 0;
    s[tid] = v;
    __syncthreads();
    for (int off = 1; off < 256; off <<= 1) {
        int x = (tid >= off) ? s[tid - off] : 0;
        __syncthreads();
        s[tid] += x;
        __syncthreads();
    }
    if (tid < NB) g_boff[tid] = s[tid] - v;       // exclusive
}

__global__ void rowptr_kernel() {                 // grid NB, block 256
    __shared__ int s[256];
    int tid = threadIdx.x;
    int i = blockIdx.x * 256 + tid;
    int v = (i < NN) ? g_deg[i] : 0;
    s[tid] = v;
    __syncthreads();
    for (int off = 1; off < 256; off <<= 1) {
        int x = (tid >= off) ? s[tid - off] : 0;
        __syncthreads();
        s[tid] += x;
        __syncthreads();
    }
    int excl = s[tid] - v + g_boff[blockIdx.x];
    if (i < NN) { g_rowptr[i] = excl; g_cursor[i] = excl; }
    if (i == NN - 1) g_rowptr[NN] = EE;
}

__global__ void scatter_kernel(const int* __restrict__ eidx,
                               const float* __restrict__ ea) {
    int e = blockIdx.x * blockDim.x + threadIdx.x;
    if (e >= EE) return;
    int s = __ldg(eidx + e);
    int d = __ldg(eidx + EE + e);
    float a0 = __ldg(ea + 2 * e);
    float a1 = __ldg(ea + 2 * e + 1);
    int pos = atomicAdd(&g_cursor[d], 1);
    g_csr[pos] = make_float4(__int_as_float(s), a0, a1, 0.f);
}

// ---------------- layer-0 small zeroing (pooled + bn stats) ----------------
__global__ void smallzero_kernel() {
    int i = blockIdx.x * blockDim.x + threadIdx.x;
    if (i < NGRP * HH) g_pooled[i] = 0.f;
    if (i < HH) { g_sum[i] = 0.0; g_sumsq[i] = 0.0; }
}

// ---------------- layer prep (layers 1..): h += vn[batch]; zero pooled+stats ----------------
__global__ void layerprep_kernel(const int* __restrict__ batch) {
    int gid = blockIdx.x * blockDim.x + threadIdx.x;
    if (gid < NGRP * HH / 4)
        *((float4*)g_pooled + gid) = make_float4(0.f, 0.f, 0.f, 0.f);
    if (gid < HH) { g_sum[gid] = 0.0; g_sumsq[gid] = 0.0; }
    int w = gid >> 5;
    if (w >= NN) return;
    int lane = threadIdx.x & 31;
    int c = lane * 4;
    int g = batch[w];
    float4* hp = (float4*)(g_h + (size_t)w * HH + c);
    float4 v = *hp;
    float4 a = *((const float4*)(g_vn + (size_t)g * HH + c));
    v.x += a.x; v.y += a.y; v.z += a.z; v.w += a.w;
    *hp = v;
}

// ---------------- proj: h = x @ proj_w + proj_b ----------------
__global__ void proj_kernel(const float* __restrict__ X,
                            const float* __restrict__ W,
                            const float* __restrict__ B) {
    __shared__ float Xs[64][IND];
    int row0 = blockIdx.x * 64;
    for (int i = threadIdx.x; i < 64 * IND / 4; i += blockDim.x) {
        int r = i >> 4, c4 = i & 15;
        float4 v = make_float4(0.f, 0.f, 0.f, 0.f);
        int row = row0 + r;
        if (row < NN) v = *(const float4*)(X + (size_t)row * IND + c4 * 4);
        *(float4*)&Xs[r][c4 * 4] = v;
    }
    __syncthreads();
    int tx = threadIdx.x & 31, ty = threadIdx.x >> 5;
    int col = tx * 4;
    float acc[8][4];
#pragma unroll
    for (int r = 0; r < 8; r++)
#pragma unroll
        for (int c = 0; c < 4; c++) acc[r][c] = 0.f;
#pragma unroll 4
    for (int k = 0; k < IND; k++) {
        float4 w = __ldg((const float4*)(W + (size_t)k * HH + col));
#pragma unroll
        for (int r = 0; r < 8; r++) {
            float a = Xs[ty * 8 + r][k];
            acc[r][0] = fmaf(a, w.x, acc[r][0]);
            acc[r][1] = fmaf(a, w.y, acc[r][1]);
            acc[r][2] = fmaf(a, w.z, acc[r][2]);
            acc[r][3] = fmaf(a, w.w, acc[r][3]);
        }
    }
    float4 b = __ldg((const float4*)(B + col));
#pragma unroll
    for (int r = 0; r < 8; r++) {
        int row = row0 + ty * 8 + r;
        if (row < NN) {
            float4 o = make_float4(acc[r][0] + b.x, acc[r][1] + b.y,
                                   acc[r][2] + b.z, acc[r][3] + b.w);
            *(float4*)(g_h + (size_t)row * HH + col) = o;
        }
    }
}

// ---------------- node MLP GEMM: tf32 MMA; stage 0 fuses CSR aggregation ----------------
// stage 0: As[r] = h[n] + sum_e relu(h[src]+e);  g_t = relu(As @ W + b)
// stage 1: g_z = g_t @ W + b
__global__ void __launch_bounds__(256) mlp_kernel(const float* __restrict__ W,
                                                  const float* __restrict__ B,
                                                  const float* __restrict__ ew,
                                                  const float* __restrict__ eb,
                                                  int stage) {
    extern __shared__ float smem_dyn[];
    float* As = smem_dyn;                  // 64 x AS_LD
    float* Ws = smem_dyn + 64 * AS_LD;     // 128 x WS_LD
    float* out = (stage == 0) ? g_t : g_z;
    int row0 = blockIdx.x * 64;

    // weight tile (coalesced, L2-served)
    for (int i = threadIdx.x; i < 128 * 32; i += 256) {
        int r = i >> 5, c4 = i & 31;
        float4 v = __ldg((const float4*)(W + (size_t)r * HH + c4 * 4));
        *(float4*)(Ws + r * WS_LD + c4 * 4) = v;
    }

    int w = threadIdx.x >> 5;
    int lane = threadIdx.x & 31;
    int cc = lane * 4;

    if (stage == 0) {
        // fused aggregation: warp w computes rows w*8 .. w*8+7 of the A tile
        float4 w0 = __ldg((const float4*)(ew + cc));
        float4 w1 = __ldg((const float4*)(ew + HH + cc));
        float4 bb = __ldg((const float4*)(eb + cc));
#pragma unroll
        for (int k = 0; k < 8; k++) {
            int r = w * 8 + k;
            int node = row0 + r;
            float4 acc = make_float4(0.f, 0.f, 0.f, 0.f);
            if (node < NN) {
                acc = *(const float4*)(g_h + (size_t)node * HH + cc);
                int beg = g_rowptr[node], end = g_rowptr[node + 1];
                int e = beg;
                for (; e + 4 <= end; e += 4) {
                    float4 r0 = g_csr[e];
                    float4 r1 = g_csr[e + 1];
                    float4 r2 = g_csr[e + 2];
                    float4 r3 = g_csr[e + 3];
                    float4 h0 = *(const float4*)(g_h + (size_t)__float_as_int(r0.x) * HH + cc);
                    float4 h1 = *(const float4*)(g_h + (size_t)__float_as_int(r1.x) * HH + cc);
                    float4 h2 = *(const float4*)(g_h + (size_t)__float_as_int(r2.x) * HH + cc);
                    float4 h3 = *(const float4*)(g_h + (size_t)__float_as_int(r3.x) * HH + cc);
                    msg_acc(acc, h0, r0.y, r0.z, w0, w1, bb);
                    msg_acc(acc, h1, r1.y, r1.z, w0, w1, bb);
                    msg_acc(acc, h2, r2.y, r2.z, w0, w1, bb);
                    msg_acc(acc, h3, r3.y, r3.z, w0, w1, bb);
                }
                for (; e < end; e++) {
                    float4 r0 = g_csr[e];
                    float4 h0 = *(const float4*)(g_h + (size_t)__float_as_int(r0.x) * HH + cc);
                    msg_acc(acc, h0, r0.y, r0.z, w0, w1, bb);
                }
            }
            *(float4*)(As + r * AS_LD + cc) = acc;
        }
    } else {
        for (int i = threadIdx.x; i < 64 * 32; i += 256) {
            int r = i >> 5, c4 = i & 31;
            int row = row0 + r;
            float4 v = make_float4(0.f, 0.f, 0.f, 0.f);
            if (row < NN) v = *(const float4*)(g_t + (size_t)row * HH + c4 * 4);
            *(float4*)(As + r * AS_LD + c4 * 4) = v;
        }
    }
    __syncthreads();

    int g = lane >> 2, t = lane & 3;
    int wr = (w & 3) * 16;
    int wc = (w >> 2) * 64;

    float acc[8][4];
#pragma unroll
    for (int j = 0; j < 8; j++)
#pragma unroll
        for (int c = 0; c < 4; c++) acc[j][c] = 0.f;

#pragma unroll 2
    for (int k0 = 0; k0 < HH; k0 += 8) {
        float af[4];
        af[0] = As[(wr + g) * AS_LD + k0 + t];
        af[1] = As[(wr + g + 8) * AS_LD + k0 + t];
        af[2] = As[(wr + g) * AS_LD + k0 + t + 4];
        af[3] = As[(wr + g + 8) * AS_LD + k0 + t + 4];
        uint32_t ah[4], al[4];
#pragma unroll
        for (int i = 0; i < 4; i++) tf32split(af[i], ah[i], al[i]);
#pragma unroll
        for (int j = 0; j < 8; j++) {
            int n = wc + j * 8 + g;
            float bf0 = Ws[(k0 + t) * WS_LD + n];
            float bf1 = Ws[(k0 + t + 4) * WS_LD + n];
            uint32_t bh0, bl0, bh1, bl1;
            tf32split(bf0, bh0, bl0);
            tf32split(bf1, bh1, bl1);
            mma8(acc[j], ah, bh0, bh1);
            mma8(acc[j], al, bh0, bh1);
            mma8(acc[j], ah, bl0, bl1);
        }
    }

    int r_lo = row0 + wr + g;
    int r_hi = r_lo + 8;
#pragma unroll
    for (int j = 0; j < 8; j++) {
        int n = wc + j * 8 + 2 * t;
        float bv0 = __ldg(B + n), bv1 = __ldg(B + n + 1);
        float2 v0 = make_float2(acc[j][0] + bv0, acc[j][1] + bv1);
        float2 v1 = make_float2(acc[j][2] + bv0, acc[j][3] + bv1);
        if (stage == 0) {
            v0.x = fmaxf(v0.x, 0.f); v0.y = fmaxf(v0.y, 0.f);
            v1.x = fmaxf(v1.x, 0.f); v1.y = fmaxf(v1.y, 0.f);
        }
        if (r_lo < NN) *(float2*)(out + (size_t)r_lo * HH + n) = v0;
        if (r_hi < NN) *(float2*)(out + (size_t)r_hi * HH + n) = v1;
    }
}

// ---------------- batch-norm statistics ----------------
__global__ void stats_kernel() {
    int col = threadIdx.x;  // 128 threads
    float s = 0.f, s2 = 0.f;
    for (int r = blockIdx.x; r < NN; r += gridDim.x) {
        float v = g_z[(size_t)r * HH + col];
        s += v;
        s2 += v * v;
    }
    atomicAdd(&g_sum[col], (double)s);
    atomicAdd(&g_sumsq[col], (double)s2);
}

__global__ void bnfin_kernel(const float* __restrict__ gamma,
                             const float* __restrict__ beta) {
    int c = threadIdx.x;
    double mean = g_sum[c] / (double)NN;
    double var = g_sumsq[c] / (double)NN - mean * mean;
    float sc = gamma[c] * rsqrtf((float)var + BN_EPS);
    g_scale[c] = sc;
    g_shift[c] = fmaf(-(float)mean, sc, beta[c]);
}

// ---------------- h = relu(z*scale+shift), pooled[batch] += h ----------------
__global__ void bnrelu_kernel(const int* __restrict__ batch,
                              float* __restrict__ outh_override) {
    int w = (blockIdx.x * blockDim.x + threadIdx.x) >> 5;
    if (w >= NN) return;
    int lane = threadIdx.x & 31;
    int c = lane * 4;
    int g = batch[w];
    float* outh = outh_override ? outh_override : g_h;
    float4 z = *(const float4*)(g_z + (size_t)w * HH + c);
    float4 sc = *(const float4*)(g_scale + c);
    float4 sh = *(const float4*)(g_shift + c);
    float4 h;
    h.x = fmaxf(fmaf(z.x, sc.x, sh.x), 0.f);
    h.y = fmaxf(fmaf(z.y, sc.y, sh.y), 0.f);
    h.z = fmaxf(fmaf(z.z, sc.z, sh.z), 0.f);
    h.w = fmaxf(fmaf(z.w, sc.w, sh.w), 0.f);
    *(float4*)(outh + (size_t)w * HH + c) = h;
    red4(g_pooled + (size_t)g * HH + c, h);
}

// ---------------- virtual-node MLP ----------------
__global__ void vn_kernel(const float* __restrict__ W1, const float* __restrict__ B1,
                          const float* __restrict__ W2, const float* __restrict__ B2) {
    __shared__ float ps[HH];
    __shared__ float t1[HH];
    int g = blockIdx.x, c = threadIdx.x;
    ps[c] = g_pooled[(size_t)g * HH + c];
    __syncthreads();
    float acc = B1[c];
#pragma unroll 4
    for (int k = 0; k < HH; k++) acc = fmaf(ps[k], __ldg(W1 + (size_t)k * HH + c), acc);
    t1[c] = fmaxf(acc, 0.f);
    __syncthreads();
    float acc2 = B2[c];
#pragma unroll 4
    for (int k = 0; k < HH; k++) acc2 = fmaf(t1[k], __ldg(W2 + (size_t)k * HH + c), acc2);
    g_vn[(size_t)g * HH + c] += acc2;
}

// ---------------- final: graph_emb = pooled / max(counts,1) ----------------
__global__ void emb_kernel(float* __restrict__ out) {
    int i = blockIdx.x * blockDim.x + threadIdx.x;
    if (i < NGRP * HH) {
        int g = i / HH;
        out[i] = g_pooled[i] / fmaxf(g_counts[g], 1.f);
    }
}

// ---------------- host ----------------
extern "C" void kernel_launch(void* const* d_in, const int* in_sizes, int n_in,
                              void* d_out, int out_size) {
    (void)n_in; (void)out_size;
    bool dict = (in_sizes[2] > 100000);
    const float *x, *ea, *pw, *pb, *ew, *eb, *cw1, *cb1, *cw2, *cb2;
    const float *gam, *bet, *vw1, *vb1, *vw2, *vb2;
    const int *eidx, *bat;
    if (dict) {
        x   = (const float*)d_in[0];  ea  = (const float*)d_in[1];
        eidx= (const int*)  d_in[2];  bat = (const int*)  d_in[3];
        pw  = (const float*)d_in[4];  pb  = (const float*)d_in[5];
        ew  = (const float*)d_in[6];  eb  = (const float*)d_in[7];
        cw1 = (const float*)d_in[8];  cb1 = (const float*)d_in[9];
        cw2 = (const float*)d_in[10]; cb2 = (const float*)d_in[11];
        gam = (const float*)d_in[12]; bet = (const float*)d_in[13];
        vw1 = (const float*)d_in[14]; vb1 = (const float*)d_in[15];
        vw2 = (const float*)d_in[16]; vb2 = (const float*)d_in[17];
    } else {
        x   = (const float*)d_in[0];  ea  = (const float*)d_in[1];
        pw  = (const float*)d_in[2];  pb  = (const float*)d_in[3];
        ew  = (const float*)d_in[4];  eb  = (const float*)d_in[5];
        cw1 = (const float*)d_in[6];  cb1 = (const float*)d_in[7];
        cw2 = (const float*)d_in[8];  cb2 = (const float*)d_in[9];
        gam = (const float*)d_in[10]; bet = (const float*)d_in[11];
        vw1 = (const float*)d_in[12]; vb1 = (const float*)d_in[13];
        vw2 = (const float*)d_in[14]; vb2 = (const float*)d_in[15];
        eidx= (const int*)  d_in[16]; bat = (const int*)  d_in[17];
    }
    float* out = (float*)d_out;

    cudaFuncSetAttribute(mlp_kernel, cudaFuncAttributeMaxDynamicSharedMemorySize, SMEM_MLP);

    // one-time prep: counts, CSR build, proj
    zero_init_kernel<<<256, 256>>>();
    counts_kernel<<<(NN + 255) / 256, 256>>>(bat);
    deg_kernel<<<(EE + 255) / 256, 256>>>(eidx);
    blocksum_kernel<<<NB, 256>>>();
    bscan_kernel<<<1, 256>>>();
    rowptr_kernel<<<NB, 256>>>();
    scatter_kernel<<<(EE + 255) / 256, 256>>>(eidx, ea);
    proj_kernel<<<(NN + 63) / 64, 256>>>(x, pw, pb);

    for (int i = 0; i < NL; i++) {
        if (i == 0) smallzero_kernel<<<256, 256>>>();
        else        layerprep_kernel<<<(NN * 32 + 255) / 256, 256>>>(bat);
        mlp_kernel<<<(NN + 63) / 64, 256, SMEM_MLP>>>(cw1 + (size_t)i * HH * HH, cb1 + i * HH, ew, eb, 0);
        mlp_kernel<<<(NN + 63) / 64, 256, SMEM_MLP>>>(cw2 + (size_t)i * HH * HH, cb2 + i * HH, ew, eb, 1);
        stats_kernel<<<256, 128>>>();
        bnfin_kernel<<<1, 128>>>(gam + i * HH, bet + i * HH);
        bnrelu_kernel<<<(NN * 32 + 255) / 256, 256>>>(bat, (i == NL - 1) ? out : nullptr);
        if (i < NL - 1) vn_kernel<<<NGRP, 128>>>(vw1, vb1, vw2, vb2);
    }
    emb_kernel<<<(NGRP * HH + 255) / 256, 256>>>(out + (size_t)NN * HH);
}

// round 15
// speedup vs baseline: 1.1361x; 1.1361x over previous
#include <cuda_runtime.h>
#include <cstdint>

#define NN 50000
#define EE 600000
#define IND 64
#define HH 128
#define NGRP 512
#define NL 3
#define BN_EPS 1e-5f
#define NB 196                       // ceil(NN/256)

#define AS_LD 132
#define WS_LD 136
#define SMEM_MLP ((64 * AS_LD + 128 * WS_LD) * 4)

// ---------------- scratch (static device arrays; no allocation) ----------------
__device__ float g_h[(size_t)NN * HH];
__device__ float g_agg[(size_t)NN * HH];
__device__ float g_t[(size_t)NN * HH];
__device__ float g_z[(size_t)NN * HH];
__device__ float g_vn[(size_t)NGRP * HH];
__device__ float g_pooled[(size_t)NGRP * HH];
__device__ double g_sum[HH];
__device__ double g_sumsq[HH];
__device__ float g_scale[HH];
__device__ float g_shift[HH];
__device__ float g_counts[NGRP];
// CSR scratch
__device__ int g_deg[NN];
__device__ int g_bsum[256];
__device__ int g_boff[256];
__device__ int g_rowptr[NN + 1];
__device__ int g_cursor[NN];
__device__ float4 g_csr[EE];         // (src_bits, a0, a1, pad)

__device__ __forceinline__ void red4(float* p, float4 v) {
    asm volatile("red.global.add.v4.f32 [%0], {%1,%2,%3,%4};"
                 :: "l"(p), "f"(v.x), "f"(v.y), "f"(v.z), "f"(v.w) : "memory");
}

__device__ __forceinline__ void tf32split(float x, uint32_t& hi, uint32_t& lo) {
    asm("cvt.rna.tf32.f32 %0, %1;" : "=r"(hi) : "f"(x));
    float r = x - __uint_as_float(hi);
    asm("cvt.rna.tf32.f32 %0, %1;" : "=r"(lo) : "f"(r));
}

__device__ __forceinline__ uint32_t tf32round(float x) {
    uint32_t v;
    asm("cvt.rna.tf32.f32 %0, %1;" : "=r"(v) : "f"(x));
    return v;
}

__device__ __forceinline__ void mma8(float* c, const uint32_t* a, uint32_t b0, uint32_t b1) {
    asm volatile("mma.sync.aligned.m16n8k8.row.col.f32.tf32.tf32.f32 "
                 "{%0,%1,%2,%3}, {%4,%5,%6,%7}, {%8,%9}, {%0,%1,%2,%3};"
                 : "+f"(c[0]), "+f"(c[1]), "+f"(c[2]), "+f"(c[3])
                 : "r"(a[0]), "r"(a[1]), "r"(a[2]), "r"(a[3]), "r"(b0), "r"(b1));
}

// ---------------- one-time init ----------------
__global__ void zero_init_kernel() {
    int i = blockIdx.x * blockDim.x + threadIdx.x;   // 65536 threads
    if (i < NGRP * HH) g_vn[i] = 0.f;
    if (i < NGRP) g_counts[i] = 0.f;
    if (i < NN) g_deg[i] = 0;
}

__global__ void counts_kernel(const int* __restrict__ batch) {
    int i = blockIdx.x * blockDim.x + threadIdx.x;
    if (i < NN) atomicAdd(&g_counts[batch[i]], 1.f);
}

__global__ void deg_kernel(const int* __restrict__ eidx) {
    int e = blockIdx.x * blockDim.x + threadIdx.x;
    if (e < EE) atomicAdd(&g_deg[eidx[EE + e]], 1);
}

// ---- fast 3-stage scan ----
__global__ void blocksum_kernel() {               // grid NB, block 256
    __shared__ int s[256];
    int tid = threadIdx.x;
    int i = blockIdx.x * 256 + tid;
    s[tid] = (i < NN) ? g_deg[i] : 0;
    __syncthreads();
    for (int off = 128; off > 0; off >>= 1) {
        if (tid < off) s[tid] += s[tid + off];
        __syncthreads();
    }
    if (tid == 0) g_bsum[blockIdx.x] = s[0];
}

__global__ void bscan_kernel() {                  // 1 block, 256 threads
    __shared__ int s[256];
    int tid = threadIdx.x;
    int v = (tid < NB) ? g_bsum[tid] : 0;
    s[tid] = v;
    __syncthreads();
    for (int off = 1; off < 256; off <<= 1) {
        int x = (tid >= off) ? s[tid - off] : 0;
        __syncthreads();
        s[tid] += x;
        __syncthreads();
    }
    if (tid < NB) g_boff[tid] = s[tid] - v;       // exclusive
}

__global__ void rowptr_kernel() {                 // grid NB, block 256
    __shared__ int s[256];
    int tid = threadIdx.x;
    int i = blockIdx.x * 256 + tid;
    int v = (i < NN) ? g_deg[i] : 0;
    s[tid] = v;
    __syncthreads();
    for (int off = 1; off < 256; off <<= 1) {
        int x = (tid >= off) ? s[tid - off] : 0;
        __syncthreads();
        s[tid] += x;
        __syncthreads();
    }
    int excl = s[tid] - v + g_boff[blockIdx.x];
    if (i < NN) { g_rowptr[i] = excl; g_cursor[i] = excl; }
    if (i == NN - 1) g_rowptr[NN] = EE;
}

__global__ void scatter_kernel(const int* __restrict__ eidx,
                               const float* __restrict__ ea) {
    int e = blockIdx.x * blockDim.x + threadIdx.x;
    if (e >= EE) return;
    int s = __ldg(eidx + e);
    int d = __ldg(eidx + EE + e);
    float a0 = __ldg(ea + 2 * e);
    float a1 = __ldg(ea + 2 * e + 1);
    int pos = atomicAdd(&g_cursor[d], 1);
    g_csr[pos] = make_float4(__int_as_float(s), a0, a1, 0.f);
}

// ---------------- per-layer small zeroing (pooled + bn stats) ----------------
__global__ void smallzero_kernel() {
    int i = blockIdx.x * blockDim.x + threadIdx.x;
    if (i < NGRP * HH) g_pooled[i] = 0.f;
    if (i < HH) { g_sum[i] = 0.0; g_sumsq[i] = 0.0; }
}

// ---------------- layer prep: h += vn[batch] (in place) ----------------
__global__ void layerprep_kernel(const int* __restrict__ batch) {
    int w = (blockIdx.x * blockDim.x + threadIdx.x) >> 5;
    if (w >= NN) return;
    int lane = threadIdx.x & 31;
    int c = lane * 4;
    int g = batch[w];
    float4* hp = (float4*)(g_h + (size_t)w * HH + c);
    float4 v = *hp;
    float4 a = *((const float4*)(g_vn + (size_t)g * HH + c));
    v.x += a.x; v.y += a.y; v.z += a.z; v.w += a.w;
    *hp = v;
}

// ---------------- proj: h = x @ proj_w + proj_b ----------------
__global__ void proj_kernel(const float* __restrict__ X,
                            const float* __restrict__ W,
                            const float* __restrict__ B) {
    __shared__ float Xs[64][IND];
    int row0 = blockIdx.x * 64;
    for (int i = threadIdx.x; i < 64 * IND / 4; i += blockDim.x) {
        int r = i >> 4, c4 = i & 15;
        float4 v = make_float4(0.f, 0.f, 0.f, 0.f);
        int row = row0 + r;
        if (row < NN) v = *(const float4*)(X + (size_t)row * IND + c4 * 4);
        *(float4*)&Xs[r][c4 * 4] = v;
    }
    __syncthreads();
    int tx = threadIdx.x & 31, ty = threadIdx.x >> 5;
    int col = tx * 4;
    float acc[8][4];
#pragma unroll
    for (int r = 0; r < 8; r++)
#pragma unroll
        for (int c = 0; c < 4; c++) acc[r][c] = 0.f;
#pragma unroll 4
    for (int k = 0; k < IND; k++) {
        float4 w = __ldg((const float4*)(W + (size_t)k * HH + col));
#pragma unroll
        for (int r = 0; r < 8; r++) {
            float a = Xs[ty * 8 + r][k];
            acc[r][0] = fmaf(a, w.x, acc[r][0]);
            acc[r][1] = fmaf(a, w.y, acc[r][1]);
            acc[r][2] = fmaf(a, w.z, acc[r][2]);
            acc[r][3] = fmaf(a, w.w, acc[r][3]);
        }
    }
    float4 b = __ldg((const float4*)(B + col));
#pragma unroll
    for (int r = 0; r < 8; r++) {
        int row = row0 + ty * 8 + r;
        if (row < NN) {
            float4 o = make_float4(acc[r][0] + b.x, acc[r][1] + b.y,
                                   acc[r][2] + b.z, acc[r][3] + b.w);
            *(float4*)(g_h + (size_t)row * HH + col) = o;
        }
    }
}

// ---------------- CSR aggregation: g_agg[n] = h[n] + sum_e relu(h[src]+e) ----------------
__global__ void agg_kernel(const float* __restrict__ ew,
                           const float* __restrict__ eb) {
    int n = (blockIdx.x * blockDim.x + threadIdx.x) >> 5;
    if (n >= NN) return;
    int lane = threadIdx.x & 31;
    int c = lane * 4;
    float4 acc = *(const float4*)(g_h + (size_t)n * HH + c);
    float4 w0 = __ldg((const float4*)(ew + c));
    float4 w1 = __ldg((const float4*)(ew + HH + c));
    float4 bb = __ldg((const float4*)(eb + c));
    int beg = g_rowptr[n], end = g_rowptr[n + 1];
    int e = beg;
    for (; e + 2 <= end; e += 2) {
        float4 r0 = g_csr[e];
        float4 r1 = g_csr[e + 1];
        int s0 = __float_as_int(r0.x);
        int s1 = __float_as_int(r1.x);
        float4 h0 = *(const float4*)(g_h + (size_t)s0 * HH + c);
        float4 h1 = *(const float4*)(g_h + (size_t)s1 * HH + c);
        acc.x += fmaxf(h0.x + fmaf(r0.y, w0.x, fmaf(r0.z, w1.x, bb.x)), 0.f);
        acc.y += fmaxf(h0.y + fmaf(r0.y, w0.y, fmaf(r0.z, w1.y, bb.y)), 0.f);
        acc.z += fmaxf(h0.z + fmaf(r0.y, w0.z, fmaf(r0.z, w1.z, bb.z)), 0.f);
        acc.w += fmaxf(h0.w + fmaf(r0.y, w0.w, fmaf(r0.z, w1.w, bb.w)), 0.f);
        acc.x += fmaxf(h1.x + fmaf(r1.y, w0.x, fmaf(r1.z, w1.x, bb.x)), 0.f);
        acc.y += fmaxf(h1.y + fmaf(r1.y, w0.y, fmaf(r1.z, w1.y, bb.y)), 0.f);
        acc.z += fmaxf(h1.z + fmaf(r1.y, w0.z, fmaf(r1.z, w1.z, bb.z)), 0.f);
        acc.w += fmaxf(h1.w + fmaf(r1.y, w0.w, fmaf(r1.z, w1.w, bb.w)), 0.f);
    }
    if (e < end) {
        float4 r0 = g_csr[e];
        int s0 = __float_as_int(r0.x);
        float4 h0 = *(const float4*)(g_h + (size_t)s0 * HH + c);
        acc.x += fmaxf(h0.x + fmaf(r0.y, w0.x, fmaf(r0.z, w1.x, bb.x)), 0.f);
        acc.y += fmaxf(h0.y + fmaf(r0.y, w0.y, fmaf(r0.z, w1.y, bb.y)), 0.f);
        acc.z += fmaxf(h0.z + fmaf(r0.y, w0.z, fmaf(r0.z, w1.z, bb.z)), 0.f);
        acc.w += fmaxf(h0.w + fmaf(r0.y, w0.w, fmaf(r0.z, w1.w, bb.w)), 0.f);
    }
    *(float4*)(g_agg + (size_t)n * HH + c) = acc;
}

// ---------------- node MLP GEMM: tf32 MMA, 2-term split (A split, B rounded) ----------------
__global__ void __launch_bounds__(256) mlp_kernel(const float* __restrict__ W,
                                                  const float* __restrict__ B,
                                                  int stage) {
    extern __shared__ float smem_dyn[];
    float* As = smem_dyn;                  // 64 x AS_LD
    float* Ws = smem_dyn + 64 * AS_LD;     // 128 x WS_LD
    const float* A = (stage == 0) ? g_agg : g_t;
    float* out = (stage == 0) ? g_t : g_z;
    int row0 = blockIdx.x * 64;

    for (int i = threadIdx.x; i < 64 * 32; i += 256) {
        int r = i >> 5, c4 = i & 31;
        int row = row0 + r;
        float4 v = make_float4(0.f, 0.f, 0.f, 0.f);
        if (row < NN) v = *(const float4*)(A + (size_t)row * HH + c4 * 4);
        *(float4*)(As + r * AS_LD + c4 * 4) = v;
    }
    for (int i = threadIdx.x; i < 128 * 32; i += 256) {
        int r = i >> 5, c4 = i & 31;
        float4 v = __ldg((const float4*)(W + (size_t)r * HH + c4 * 4));
        *(float4*)(Ws + r * WS_LD + c4 * 4) = v;
    }
    __syncthreads();

    int w = threadIdx.x >> 5;
    int lane = threadIdx.x & 31;
    int g = lane >> 2, t = lane & 3;
    int wr = (w & 3) * 16;
    int wc = (w >> 2) * 64;

    float acc[8][4];
#pragma unroll
    for (int j = 0; j < 8; j++)
#pragma unroll
        for (int c = 0; c < 4; c++) acc[j][c] = 0.f;

#pragma unroll 2
    for (int k0 = 0; k0 < HH; k0 += 8) {
        float af[4];
        af[0] = As[(wr + g) * AS_LD + k0 + t];
        af[1] = As[(wr + g + 8) * AS_LD + k0 + t];
        af[2] = As[(wr + g) * AS_LD + k0 + t + 4];
        af[3] = As[(wr + g + 8) * AS_LD + k0 + t + 4];
        uint32_t ah[4], al[4];
#pragma unroll
        for (int i = 0; i < 4; i++) tf32split(af[i], ah[i], al[i]);
#pragma unroll
        for (int j = 0; j < 8; j++) {
            int n = wc + j * 8 + g;
            uint32_t bh0 = tf32round(Ws[(k0 + t) * WS_LD + n]);
            uint32_t bh1 = tf32round(Ws[(k0 + t + 4) * WS_LD + n]);
            mma8(acc[j], ah, bh0, bh1);   // A_hi * B
            mma8(acc[j], al, bh0, bh1);   // A_lo * B
        }
    }

    int r_lo = row0 + wr + g;
    int r_hi = r_lo + 8;
#pragma unroll
    for (int j = 0; j < 8; j++) {
        int n = wc + j * 8 + 2 * t;
        float bv0 = __ldg(B + n), bv1 = __ldg(B + n + 1);
        float2 v0 = make_float2(acc[j][0] + bv0, acc[j][1] + bv1);
        float2 v1 = make_float2(acc[j][2] + bv0, acc[j][3] + bv1);
        if (stage == 0) {
            v0.x = fmaxf(v0.x, 0.f); v0.y = fmaxf(v0.y, 0.f);
            v1.x = fmaxf(v1.x, 0.f); v1.y = fmaxf(v1.y, 0.f);
        }
        if (r_lo < NN) *(float2*)(out + (size_t)r_lo * HH + n) = v0;
        if (r_hi < NN) *(float2*)(out + (size_t)r_hi * HH + n) = v1;
    }
}

// ---------------- batch-norm statistics ----------------
__global__ void stats_kernel() {
    int col = threadIdx.x;  // 128 threads
    float s = 0.f, s2 = 0.f;
    for (int r = blockIdx.x; r < NN; r += gridDim.x) {
        float v = g_z[(size_t)r * HH + col];
        s += v;
        s2 += v * v;
    }
    atomicAdd(&g_sum[col], (double)s);
    atomicAdd(&g_sumsq[col], (double)s2);
}

__global__ void bnfin_kernel(const float* __restrict__ gamma,
                             const float* __restrict__ beta) {
    int c = threadIdx.x;
    double mean = g_sum[c] / (double)NN;
    double var = g_sumsq[c] / (double)NN - mean * mean;
    float sc = gamma[c] * rsqrtf((float)var + BN_EPS);
    g_scale[c] = sc;
    g_shift[c] = fmaf(-(float)mean, sc, beta[c]);
}

// ---------------- h = relu(z*scale+shift), pooled[batch] += h ----------------
__global__ void bnrelu_kernel(const int* __restrict__ batch,
                              float* __restrict__ outh_override) {
    int w = (blockIdx.x * blockDim.x + threadIdx.x) >> 5;
    if (w >= NN) return;
    int lane = threadIdx.x & 31;
    int c = lane * 4;
    int g = batch[w];
    float* outh = outh_override ? outh_override : g_h;
    float4 z = *(const float4*)(g_z + (size_t)w * HH + c);
    float4 sc = *(const float4*)(g_scale + c);
    float4 sh = *(const float4*)(g_shift + c);
    float4 h;
    h.x = fmaxf(fmaf(z.x, sc.x, sh.x), 0.f);
    h.y = fmaxf(fmaf(z.y, sc.y, sh.y), 0.f);
    h.z = fmaxf(fmaf(z.z, sc.z, sh.z), 0.f);
    h.w = fmaxf(fmaf(z.w, sc.w, sh.w), 0.f);
    *(float4*)(outh + (size_t)w * HH + c) = h;
    red4(g_pooled + (size_t)g * HH + c, h);
}

// ---------------- virtual-node MLP ----------------
__global__ void vn_kernel(const float* __restrict__ W1, const float* __restrict__ B1,
                          const float* __restrict__ W2, const float* __restrict__ B2) {
    __shared__ float ps[HH];
    __shared__ float t1[HH];
    int g = blockIdx.x, c = threadIdx.x;
    ps[c] = g_pooled[(size_t)g * HH + c];
    __syncthreads();
    float acc = B1[c];
#pragma unroll 4
    for (int k = 0; k < HH; k++) acc = fmaf(ps[k], __ldg(W1 + (size_t)k * HH + c), acc);
    t1[c] = fmaxf(acc, 0.f);
    __syncthreads();
    float acc2 = B2[c];
#pragma unroll 4
    for (int k = 0; k < HH; k++) acc2 = fmaf(t1[k], __ldg(W2 + (size_t)k * HH + c), acc2);
    g_vn[(size_t)g * HH + c] += acc2;
}

// ---------------- final: graph_emb = pooled / max(counts,1) ----------------
__global__ void emb_kernel(float* __restrict__ out) {
    int i = blockIdx.x * blockDim.x + threadIdx.x;
    if (i < NGRP * HH) {
        int g = i / HH;
        out[i] = g_pooled[i] / fmaxf(g_counts[g], 1.f);
    }
}

// ---------------- host ----------------
extern "C" void kernel_launch(void* const* d_in, const int* in_sizes, int n_in,
                              void* d_out, int out_size) {
    (void)n_in; (void)out_size;
    bool dict = (in_sizes[2] > 100000);
    const float *x, *ea, *pw, *pb, *ew, *eb, *cw1, *cb1, *cw2, *cb2;
    const float *gam, *bet, *vw1, *vb1, *vw2, *vb2;
    const int *eidx, *bat;
    if (dict) {
        x   = (const float*)d_in[0];  ea  = (const float*)d_in[1];
        eidx= (const int*)  d_in[2];  bat = (const int*)  d_in[3];
        pw  = (const float*)d_in[4];  pb  = (const float*)d_in[5];
        ew  = (const float*)d_in[6];  eb  = (const float*)d_in[7];
        cw1 = (const float*)d_in[8];  cb1 = (const float*)d_in[9];
        cw2 = (const float*)d_in[10]; cb2 = (const float*)d_in[11];
        gam = (const float*)d_in[12]; bet = (const float*)d_in[13];
        vw1 = (const float*)d_in[14]; vb1 = (const float*)d_in[15];
        vw2 = (const float*)d_in[16]; vb2 = (const float*)d_in[17];
    } else {
        x   = (const float*)d_in[0];  ea  = (const float*)d_in[1];
        pw  = (const float*)d_in[2];  pb  = (const float*)d_in[3];
        ew  = (const float*)d_in[4];  eb  = (const float*)d_in[5];
        cw1 = (const float*)d_in[6];  cb1 = (const float*)d_in[7];
        cw2 = (const float*)d_in[8];  cb2 = (const float*)d_in[9];
        gam = (const float*)d_in[10]; bet = (const float*)d_in[11];
        vw1 = (const float*)d_in[12]; vb1 = (const float*)d_in[13];
        vw2 = (const float*)d_in[14]; vb2 = (const float*)d_in[15];
        eidx= (const int*)  d_in[16]; bat = (const int*)  d_in[17];
    }
    float* out = (float*)d_out;

    cudaFuncSetAttribute(mlp_kernel, cudaFuncAttributeMaxDynamicSharedMemorySize, SMEM_MLP);

    // one-time prep: counts, CSR build, proj
    zero_init_kernel<<<256, 256>>>();
    counts_kernel<<<(NN + 255) / 256, 256>>>(bat);
    deg_kernel<<<(EE + 255) / 256, 256>>>(eidx);
    blocksum_kernel<<<NB, 256>>>();
    bscan_kernel<<<1, 256>>>();
    rowptr_kernel<<<NB, 256>>>();
    scatter_kernel<<<(EE + 255) / 256, 256>>>(eidx, ea);
    proj_kernel<<<(NN + 63) / 64, 256>>>(x, pw, pb);

    for (int i = 0; i < NL; i++) {
        smallzero_kernel<<<256, 256>>>();
        if (i > 0) layerprep_kernel<<<(NN * 32 + 255) / 256, 256>>>(bat);
        agg_kernel<<<(NN * 32 + 255) / 256, 256>>>(ew, eb);
        mlp_kernel<<<(NN + 63) / 64, 256, SMEM_MLP>>>(cw1 + (size_t)i * HH * HH, cb1 + i * HH, 0);
        mlp_kernel<<<(NN + 63) / 64, 256, SMEM_MLP>>>(cw2 + (size_t)i * HH * HH, cb2 + i * HH, 1);
        stats_kernel<<<256, 128>>>();
        bnfin_kernel<<<1, 128>>>(gam + i * HH, bet + i * HH);
        bnrelu_kernel<<<(NN * 32 + 255) / 256, 256>>>(bat, (i == NL - 1) ? out : nullptr);
        if (i < NL - 1) vn_kernel<<<NGRP, 128>>>(vw1, vb1, vw2, vb2);
    }
    emb_kernel<<<(NGRP * HH + 255) / 256, 256>>>(out + (size_t)NN * HH);
}